// round 17
// baseline (speedup 1.0000x reference)
#include <cuda_runtime.h>

// CARAFE: features [2,64,64,256] f32, masks [2,128,128,25] f32, k=5, group=1.
// Nearest 64->128 half-pixel => src = dst >> 1.
// R17: R16's two-source-row body (vertical patch reuse, dual pixel streams
//      sharing window registers) at the proven 1024-block launch shape:
//      SEGW=4 x 2 rows = 8 px/block, grid (16, 32, 2).

#define FH 64
#define FW 64
#define C2 128     // 256 channels / 2 (float2 groups)
#define OH 128
#define OW 128
#define KK 25
#define SEGW 4     // source cols per block
#define NROW 2     // source rows per block

__device__ __forceinline__ void fma2s(float2& a, const float2 f, const float m) {
    a.x = fmaf(f.x, m, a.x);
    a.y = fmaf(f.y, m, a.y);
}

template<bool CHK>
__device__ __forceinline__ void carafe_body(int seg, int hs0, int b,
                                            const float2* __restrict__ F,
                                            float2* __restrict__ O,
                                            const float* __restrict__ smask,
                                            int c2)
{
    const int ws0 = seg * SEGW;
    const float2 z = make_float2(0.f, 0.f);

    // feature base at (row hs0-2, col ws0-2); all accesses immediate offsets.
    const float2* fb = F + ((b * FH + (hs0 - 2)) * FW + (ws0 - 2)) * C2 + c2;

    bool rok[6];
    #pragma unroll
    for (int r = 0; r < 6; r++) {
        int hr = hs0 - 2 + r;
        rok[r] = CHK ? (hr >= 0 && hr < FH) : true;
    }

    // 6-row x 5-slot rotating window: col (ws0-2+j) -> slot j (mod 5)
    float2 w[6][5];
    #pragma unroll
    for (int j = 0; j < 5; j++) {
        bool cok = CHK ? ((ws0 - 2 + j) >= 0 && (ws0 - 2 + j) < FW) : true;
        #pragma unroll
        for (int r = 0; r < 6; r++)
            w[r][j] = (rok[r] && cok) ? fb[(r * FW + j) * C2] : z;
    }

    float2* ob = O + ((b * OH + 2 * hs0) * OW + 2 * ws0) * C2 + c2;

    #pragma unroll
    for (int s = 0; s < SEGW; s++) {
        // masks: [srcrow2][px4][tap25][out4], source tap order p = r*5+d
        const float4* __restrict__ mp0 = (const float4*)(smask + s * (KK * 4));
        const float4* __restrict__ mp1 =
            (const float4*)(smask + (SEGW + s) * (KK * 4));

        float2 a0 = z, a1 = z, a2 = z, a3 = z;   // source row hs0
        float2 b0 = z, b1 = z, b2 = z, b3 = z;   // source row hs0+1

        // d-major sweep; streams share window registers (row r vs r+1)
        #pragma unroll
        for (int d = 0; d < 5; d++) {
            #pragma unroll
            for (int r = 0; r < 5; r++) {
                const int sl = (s + d) % 5;       // compile-time slot
                const float2 f0 = w[r][sl];
                const float2 f1 = w[r + 1][sl];
                const float4 m0 = mp0[r * 5 + d]; // LDS.128 broadcast, stream A
                const float4 m1 = mp1[r * 5 + d]; // LDS.128 broadcast, stream B
                fma2s(a0, f0, m0.x);  fma2s(b0, f1, m1.x);
                fma2s(a1, f0, m0.y);  fma2s(b1, f1, m1.y);
                fma2s(a2, f0, m0.z);  fma2s(b2, f1, m1.z);
                fma2s(a3, f0, m0.w);  fma2s(b3, f1, m1.w);
            }
        }

        ob[(2 * s) * C2]              = a0;   // out row 2*hs0
        ob[(2 * s + 1) * C2]          = a1;
        ob[(OW + 2 * s) * C2]         = a2;   // out row 2*hs0+1
        ob[(OW + 2 * s + 1) * C2]     = a3;
        ob[(2 * OW + 2 * s) * C2]     = b0;   // out row 2*hs0+2
        ob[(2 * OW + 2 * s + 1) * C2] = b1;
        ob[(3 * OW + 2 * s) * C2]     = b2;   // out row 2*hs0+3
        ob[(3 * OW + 2 * s + 1) * C2] = b3;

        if (s < SEGW - 1) {
            // refill col (ws0+s+3) into slot s%5; consumed at iter s+1, d=4
            const bool cok = CHK ? ((ws0 + s + 3) < FW) : true;
            #pragma unroll
            for (int r = 0; r < 6; r++)
                w[r][s % 5] = (rok[r] && cok) ? fb[(r * FW + (s + 5)) * C2] : z;
        }
    }
}

__global__ __launch_bounds__(128)
void carafe_kernel(const float* __restrict__ features,
                   const float* __restrict__ masks,
                   float* __restrict__ out)
{
    // smask: [srcrow(2)][px(4)][p(25)][out(4)], p = r*5+d (source order)
    __shared__ __align__(16) float smask[NROW * SEGW * KK * 4];

    const int tid = threadIdx.x;
    const int seg = blockIdx.x;
    const int hs0 = blockIdx.y * NROW;
    const int b   = blockIdx.z;
    const int ws0 = seg * SEGW;

    // ---- division-free mask transpose stage ----
    // tid = row*64 + px*16 + o*4 + q  (row:0..1, px:0..3, o:0..3, q:0..3)
    // thread copies taps p = q+4k (k:0..6, p<25), all offsets immediate.
    {
        const int q   = tid & 3;
        const int o   = (tid >> 2) & 3;
        const int px  = (tid >> 4) & 3;
        const int row = tid >> 6;
        const int oy  = o >> 1;
        const int ox  = o & 1;

        const float* gm = masks
            + ((b * OH + 2 * (hs0 + row) + oy) * OW + 2 * (ws0 + px) + ox) * KK + q;
        float* sm = smask + (row * SEGW + px) * (KK * 4) + q * 4 + o;

        #pragma unroll
        for (int k = 0; k < 7; k++) {
            if (k < 6 || q == 0)
                sm[k * 16] = gm[k * 4];
        }
    }
    __syncthreads();

    const float2* F = (const float2*)features;
    float2* O = (float2*)out;

    // interior: rows hs0-2..hs0+3 valid, cols ws0-2..ws0+6 valid
    const bool interior = (seg >= 1) && (seg <= 14) && (hs0 >= 2) && (hs0 <= 60);
    if (interior)
        carafe_body<false>(seg, hs0, b, F, O, smask, tid);
    else
        carafe_body<true>(seg, hs0, b, F, O, smask, tid);
}

extern "C" void kernel_launch(void* const* d_in, const int* in_sizes, int n_in,
                              void* d_out, int out_size) {
    const float* features = (const float*)d_in[0];
    const float* masks    = (const float*)d_in[1];
    float* out            = (float*)d_out;

    dim3 grid(FW / SEGW, FH / NROW, 2);   // (16, 32, 2) = 1024 blocks x 4 warps
    carafe_kernel<<<grid, 128>>>(features, masks, out);
}